// round 17
// baseline (speedup 1.0000x reference)
#include <cuda_runtime.h>
#include <cuda_bf16.h>
#include <cuda_fp16.h>
#include <math.h>
#include <stdint.h>

#define B_  2
#define T_  4096
#define C_  768
#define H_  12
#define D_  64
#define NQKV_ 2304
#define M_  8192
#define BH_ (B_*H_)

// ---------------- device scratch (allocation-free rule) -------------------
__device__ __align__(16) __half g_xf[M_*C_];
__device__ __align__(16) __half g_wqkvT[NQKV_*C_];
__device__ __align__(16) __half g_wpT[C_*C_];
__device__ __align__(16) __half g_Qf[BH_*T_*D_];
__device__ __align__(16) __half g_Kf[BH_*T_*D_];
__device__ __align__(16) __half g_Vt[BH_*D_*T_];                // [bh][d][t]
__device__ __align__(16) __half g_Yf[M_*C_];

// ---------------- helpers -------------------------------------------------
__device__ __forceinline__ void mma16816h(float c[4], const uint32_t a[4], const uint32_t b[2]) {
    asm volatile("mma.sync.aligned.m16n8k16.row.col.f32.f16.f16.f32 "
        "{%0,%1,%2,%3}, {%4,%5,%6,%7}, {%8,%9}, {%0,%1,%2,%3};\n"
        : "+f"(c[0]), "+f"(c[1]), "+f"(c[2]), "+f"(c[3])
        : "r"(a[0]), "r"(a[1]), "r"(a[2]), "r"(a[3]), "r"(b[0]), "r"(b[1]));
}
__device__ __forceinline__ void ldsm4(uint32_t r[4], const void* p) {
    uint32_t a = (uint32_t)__cvta_generic_to_shared(p);
    asm volatile("ldmatrix.sync.aligned.m8n8.x4.shared.b16 {%0,%1,%2,%3}, [%4];"
        : "=r"(r[0]), "=r"(r[1]), "=r"(r[2]), "=r"(r[3]) : "r"(a));
}
__device__ __forceinline__ void cp16(void* dst, const void* src) {
    unsigned d = (unsigned)__cvta_generic_to_shared(dst);
    asm volatile("cp.async.cg.shared.global [%0], [%1], 16;\n" :: "r"(d), "l"(src));
}
__device__ __forceinline__ void cp_commit() { asm volatile("cp.async.commit_group;\n"); }
template<int N> __device__ __forceinline__ void cp_wait() {
    asm volatile("cp.async.wait_group %0;\n" :: "n"(N));
}
__device__ __forceinline__ uint32_t ex2h2(uint32_t v) {
    uint32_t r;
    asm("ex2.approx.f16x2 %0, %1;" : "=r"(r) : "r"(v));
    return r;
}

// ---------------- prep kernels -------------------------------------------
__global__ __launch_bounds__(256) void convert_x_kernel(const float* __restrict__ x) {
    size_t i = ((size_t)blockIdx.x * 256 + threadIdx.x) * 4;
    float4 v = *(const float4*)(x + i);
    __half2 a = __floats2half2_rn(v.x, v.y);
    __half2 b = __floats2half2_rn(v.z, v.w);
    *(__half2*)(g_xf + i)     = a;
    *(__half2*)(g_xf + i + 2) = b;
}

__global__ __launch_bounds__(256) void tsplit_kernel(const float* __restrict__ w,
                                                     int K, int N, int mode) {
    __shared__ float tile[32][33];
    __half* outf = mode == 0 ? g_wqkvT : g_wpT;
    const int n0 = blockIdx.x * 32, k0 = blockIdx.y * 32;
    const int tx = threadIdx.x & 31, ty = threadIdx.x >> 5;
#pragma unroll
    for (int r = 0; r < 32; r += 8)
        tile[ty + r][tx] = w[(size_t)(k0 + ty + r) * N + n0 + tx];
    __syncthreads();
#pragma unroll
    for (int r = 0; r < 32; r += 8) {
        size_t o = (size_t)(n0 + ty + r) * K + k0 + tx;
        outf[o] = __float2half(tile[tx][ty + r]);
    }
}

// ---------------- GEMM: 128x256 CTA tile, 64x64 warp tile, 1 CTA/SM --------
__device__ __forceinline__ void epi_qkv(int m, int n, float v0, float v1) {
    const int b = m >> 12, t = m & 4095;
    const int sec = n / C_, r = n - sec * C_;
    const int h = r >> 6, d = r & 63;
    const int bh = b * H_ + h;
    if (sec == 2) {
        size_t o = ((size_t)bh * D_ + d) * T_ + t;
        g_Vt[o]      = __float2half(v0);
        g_Vt[o + T_] = __float2half(v1);
    } else {
        size_t o = ((size_t)bh * T_ + t) * D_ + d;
        __half* dst = (sec == 0) ? g_Qf : g_Kf;
        __half2 hv = __floats2half2_rn(v0, v1);
        *(__half2*)(dst + o) = hv;
    }
}

#define GSTAGE 27648   /* halves per stage: A 128x72 (9216) | B 256x72 (18432) */

template<int MODE>
__global__ __launch_bounds__(256, 1) void gemm_kernel(float* __restrict__ out) {
    extern __shared__ __half sm[];

    const __half* Agf = (MODE == 1) ? g_xf : g_Yf;
    const __half* Bgf = (MODE == 1) ? g_wqkvT : g_wpT;

    const int tid = threadIdx.x, wid = tid >> 5, lane = tid & 31;
    const int wm = wid >> 2, wn = wid & 3;        // 2 x 4 warp grid
    const int lq = lane >> 2, cq = (lane & 3) << 1;
    const int bm = blockIdx.y * 128, bn = blockIdx.x * 256;

    const int a_loff = ((((lane >> 3) & 1) * 8 + (lane & 7)) * 72) + (lane >> 4) * 8;
    const int b_loff = (((lane >> 4) * 8 + (lane & 7)) * 72) + ((lane >> 3) & 1) * 8;

    float acc[4][8][4];
#pragma unroll
    for (int i = 0; i < 4; i++)
#pragma unroll
        for (int j = 0; j < 8; j++)
#pragma unroll
            for (int k = 0; k < 4; k++) acc[i][j][k] = 0.f;

#define LOAD_TILES(STG, K0)                                                   \
    {                                                                         \
        _Pragma("unroll")                                                     \
        for (int i_ = 0; i_ < 12; i_++) {                                     \
            int c_ = tid + 256 * i_;                                          \
            if (c_ < 1024) {            /* A: 128 rows x 8 chunks */          \
                int row_ = c_ >> 3, of_ = (c_ & 7) << 3;                      \
                cp16(sm + (STG) * GSTAGE + row_ * 72 + of_,                   \
                     Agf + (size_t)(bm + row_) * C_ + (K0) + of_);            \
            } else {                    /* B: 256 rows x 8 chunks */          \
                int idx_ = c_ - 1024;                                         \
                int row_ = idx_ >> 3, of_ = (idx_ & 7) << 3;                  \
                cp16(sm + (STG) * GSTAGE + 9216 + row_ * 72 + of_,            \
                     Bgf + (size_t)(bn + row_) * C_ + (K0) + of_);            \
            }                                                                 \
        }                                                                     \
    }

    LOAD_TILES(0, 0);  cp_commit();
    LOAD_TILES(1, 64); cp_commit();

    for (int kt = 0; kt < 12; kt++) {
        if (kt < 10) cp_wait<1>(); else cp_wait<0>();
        __syncthreads();
        if (kt + 2 < 12) { LOAD_TILES((kt + 2) % 3, (kt + 2) * 64); cp_commit(); }
        const __half* sA = sm + (kt % 3) * GSTAGE;
        const __half* sB = sA + 9216;
#pragma unroll
        for (int kc = 0; kc < 4; kc++) {
            uint32_t a4[4][4];
#pragma unroll
            for (int mc = 0; mc < 4; mc++)
                ldsm4(a4[mc], sA + (wm * 64 + mc * 16) * 72 + kc * 16 + a_loff);
#pragma unroll
            for (int nc2 = 0; nc2 < 4; nc2++) {
                uint32_t b4[4];
                ldsm4(b4, sB + (wn * 64 + nc2 * 16) * 72 + kc * 16 + b_loff);
#pragma unroll
                for (int mc = 0; mc < 4; mc++) {
                    mma16816h(acc[mc][2*nc2],   a4[mc], &b4[0]);
                    mma16816h(acc[mc][2*nc2+1], a4[mc], &b4[2]);
                }
            }
        }
    }

#pragma unroll
    for (int mc = 0; mc < 4; mc++)
#pragma unroll
        for (int nc = 0; nc < 8; nc++) {
            const int m = bm + wm * 64 + mc * 16 + lq;
            const int n = bn + wn * 64 + nc * 8 + cq;
            float* a = acc[mc][nc];
            if (MODE == 2) {
                *(float2*)&out[(size_t)m * C_ + n]       = make_float2(a[0], a[1]);
                *(float2*)&out[(size_t)(m + 8) * C_ + n] = make_float2(a[2], a[3]);
            } else {
                epi_qkv(m, n, a[0], a[1]);
                epi_qkv(m + 8, n, a[2], a[3]);
            }
        }
}
#define GEMM_SMEM (3 * GSTAGE * 2)   /* 165888 B */

// ---------------- flash attention (R16, unchanged) ---------------------------
#define SA_ 0.1803368801111204f
#define FSTAGE 9216
#define FQ_OFF (3 * FSTAGE)
#define FM_OFF (FQ_OFF + 9216)
#define FLASH_SMEM ((3 * FSTAGE + 9216) * 2 + 512)

__global__ __launch_bounds__(256, 2) void flash_kernel() {
    extern __shared__ __half fsm[];

    const int qt = (int)(gridDim.x - 1) - (int)blockIdx.x;
    const int bh = blockIdx.y;
    const int tid = threadIdx.x, wid = tid >> 5, lane = tid & 31;
    const int lq = lane >> 2, cq = (lane & 3) << 1;
    const int row0 = qt * 128 + wid * 16 + lq;

    const int b_loff = (((lane >> 4) * 8 + (lane & 7)) * 72) + ((lane >> 3) & 1) * 8;
    const int a_loff = ((((lane >> 3) & 1) * 8 + (lane & 7)) * 72) + (lane >> 4) * 8;
    const int q_woff = (wid * 16) * 72;

    __half* sQf = fsm + FQ_OFF;
    float* m_row = (float*)(fsm + FM_OFF);

    float oacc[8][4];
#pragma unroll
    for (int i = 0; i < 8; i++)
#pragma unroll
        for (int j = 0; j < 4; j++) oacc[i][j] = 0.f;
    float l0 = 0.f, l1 = 0.f;

    const __half* Kb = g_Kf + (size_t)bh * T_ * D_;
    const __half* Vb = g_Vt + (size_t)bh * D_ * T_;

#define LOADF(STG, KT)                                                        \
    {                                                                         \
        __half* bb = fsm + (STG) * FSTAGE;                                    \
        const __half* pk_ = Kb + (size_t)(KT) * 64 * D_;                      \
        _Pragma("unroll")                                                     \
        for (int c_ = tid; c_ < 512; c_ += 256) {                             \
            const int r_ = c_ >> 3, of_ = (c_ & 7) << 3;                      \
            cp16(bb + r_ * 72 + of_, pk_ + r_ * D_ + of_);                    \
            cp16(bb + 4608 + r_ * 72 + of_,                                   \
                 Vb + (size_t)r_ * T_ + (KT) * 64 + of_);                     \
        }                                                                     \
    }

    const int nkt = 2 * qt + 2;

    {
        const __half* Qp = g_Qf + ((size_t)bh * T_ + (size_t)qt * 128) * D_;
#pragma unroll
        for (int c = tid; c < 1024; c += 256) {
            const int r = c >> 3, of = (c & 7) << 3;
            cp16(sQf + r * 72 + of, Qp + r * D_ + of);
        }
    }
    LOADF(0, 0); cp_commit();
    LOADF(1, 1); cp_commit();
    cp_wait<1>(); __syncthreads();

    {
        const int r = tid >> 1, hf = tid & 1;
        const int base = r * 72 + hf * 32;
        float s = 0.f;
#pragma unroll
        for (int i = 0; i < 32; i++) {
            float q = __half2float(sQf[base + i]);
            s = fmaf(q, q, s);
        }
        s += __shfl_xor_sync(0xffffffffu, s, 1);
        if (hf == 0) {
            const float n = (float)(qt * 128 + r + 1);
            m_row[r] = sqrtf(s) * SA_ * sqrtf(2.0f * logf(n) + 1e-6f);
        }
    }
    __syncthreads();
    const float mr0 = m_row[wid * 16 + lq];
    const float mr1 = m_row[wid * 16 + lq + 8];

    for (int kt = 0; kt < nkt; kt++) {
        if (kt > 0) {
            if (kt + 1 < nkt) cp_wait<1>(); else cp_wait<0>();
            __syncthreads();
        }
        if (kt + 2 < nkt) { LOADF((kt + 2) % 3, kt + 2); cp_commit(); }

        const __half* sKf = fsm + (kt % 3) * FSTAGE;
        const __half* sVt = sKf + 4608;

        float sacc[8][4];
#pragma unroll
        for (int i = 0; i < 8; i++)
#pragma unroll
            for (int j = 0; j < 4; j++) sacc[i][j] = 0.f;
#pragma unroll
        for (int kc = 0; kc < 4; kc++) {
            uint32_t q4[4];
            ldsm4(q4, sQf + q_woff + kc * 16 + a_loff);
#pragma unroll
            for (int nc2 = 0; nc2 < 4; nc2++) {
                uint32_t k4[4];
                ldsm4(k4, sKf + nc2 * 16 * 72 + kc * 16 + b_loff);
                mma16816h(sacc[2*nc2],   q4, &k4[0]);
                mma16816h(sacc[2*nc2+1], q4, &k4[2]);
            }
        }

        if (kt >= 2 * qt) {
            const int colb = kt * 64;
#pragma unroll
            for (int nc = 0; nc < 8; nc++) {
                const int c0 = colb + nc * 8 + cq;
                if (c0     > row0)     sacc[nc][0] = -1e30f;
                if (c0 + 1 > row0)     sacc[nc][1] = -1e30f;
                if (c0     > row0 + 8) sacc[nc][2] = -1e30f;
                if (c0 + 1 > row0 + 8) sacc[nc][3] = -1e30f;
            }
        }

        uint32_t pa[4][4];
        __half2 ls0 = __float2half2_rn(0.f);
        __half2 ls1 = __float2half2_rn(0.f);
#pragma unroll
        for (int kc = 0; kc < 4; kc++) {
            const float ye0 = fmaf(sacc[2*kc][0],   SA_, -mr0);
            const float ye1 = fmaf(sacc[2*kc][1],   SA_, -mr0);
            const float ye2 = fmaf(sacc[2*kc][2],   SA_, -mr1);
            const float ye3 = fmaf(sacc[2*kc][3],   SA_, -mr1);
            const float yf0 = fmaf(sacc[2*kc+1][0], SA_, -mr0);
            const float yf1 = fmaf(sacc[2*kc+1][1], SA_, -mr0);
            const float yf2 = fmaf(sacc[2*kc+1][2], SA_, -mr1);
            const float yf3 = fmaf(sacc[2*kc+1][3], SA_, -mr1);
            __half2 he01 = __floats2half2_rn(ye0, ye1);
            __half2 he23 = __floats2half2_rn(ye2, ye3);
            __half2 hf01 = __floats2half2_rn(yf0, yf1);
            __half2 hf23 = __floats2half2_rn(yf2, yf3);
            pa[kc][0] = ex2h2(*(uint32_t*)&he01);
            pa[kc][1] = ex2h2(*(uint32_t*)&he23);
            pa[kc][2] = ex2h2(*(uint32_t*)&hf01);
            pa[kc][3] = ex2h2(*(uint32_t*)&hf23);
            ls0 = __hadd2(ls0, __hadd2(*(__half2*)&pa[kc][0], *(__half2*)&pa[kc][2]));
            ls1 = __hadd2(ls1, __hadd2(*(__half2*)&pa[kc][1], *(__half2*)&pa[kc][3]));
        }
        {
            float2 a0 = __half22float2(ls0);
            float2 a1 = __half22float2(ls1);
            l0 += a0.x + a0.y;
            l1 += a1.x + a1.y;
        }

#pragma unroll
        for (int kc = 0; kc < 4; kc++) {
#pragma unroll
            for (int dc2 = 0; dc2 < 4; dc2++) {
                uint32_t v4[4];
                ldsm4(v4, sVt + dc2 * 16 * 72 + kc * 16 + b_loff);
                mma16816h(oacc[2*dc2],   pa[kc], &v4[0]);
                mma16816h(oacc[2*dc2+1], pa[kc], &v4[2]);
            }
        }
    }

    l0 += __shfl_xor_sync(0xffffffffu, l0, 1);
    l0 += __shfl_xor_sync(0xffffffffu, l0, 2);
    l1 += __shfl_xor_sync(0xffffffffu, l1, 1);
    l1 += __shfl_xor_sync(0xffffffffu, l1, 2);
    const float inv0 = 1.f / l0, inv1 = 1.f / l1;

    const int b = bh / H_, h = bh - b * H_;
    const size_t y0 = ((size_t)b * T_ + row0) * C_ + h * D_;
    const size_t y1 = ((size_t)b * T_ + row0 + 8) * C_ + h * D_;
#pragma unroll
    for (int dc = 0; dc < 8; dc++) {
        const int col = dc * 8 + cq;
        __half2 h0 = __floats2half2_rn(oacc[dc][0] * inv0, oacc[dc][1] * inv0);
        __half2 h1 = __floats2half2_rn(oacc[dc][2] * inv1, oacc[dc][3] * inv1);
        *(__half2*)(g_Yf + y0 + col) = h0;
        *(__half2*)(g_Yf + y1 + col) = h1;
    }
}

// ---------------------------------------------------------------------------
extern "C" void kernel_launch(void* const* d_in, const int* in_sizes, int n_in,
                              void* d_out, int out_size)
{
    const float* x      = (const float*)d_in[0];
    const float* w_qkv  = (const float*)d_in[1];
    const float* w_proj = (const float*)d_in[2];
    float* out = (float*)d_out;

    convert_x_kernel<<<(M_ * C_) / (256 * 4), 256>>>(x);
    tsplit_kernel<<<dim3(NQKV_ / 32, C_ / 32), 256>>>(w_qkv, C_, NQKV_, 0);
    tsplit_kernel<<<dim3(C_ / 32, C_ / 32), 256>>>(w_proj, C_, C_, 1);

    cudaFuncSetAttribute(gemm_kernel<1>, cudaFuncAttributeMaxDynamicSharedMemorySize, GEMM_SMEM);
    cudaFuncSetAttribute(gemm_kernel<2>, cudaFuncAttributeMaxDynamicSharedMemorySize, GEMM_SMEM);
    cudaFuncSetAttribute(flash_kernel, cudaFuncAttributeMaxDynamicSharedMemorySize, FLASH_SMEM);

    gemm_kernel<1><<<dim3(NQKV_ / 256, M_ / 128), 256, GEMM_SMEM>>>(nullptr);
    flash_kernel<<<dim3(T_ / 128, BH_), 256, FLASH_SMEM>>>();
    gemm_kernel<2><<<dim3(C_ / 256, M_ / 128), 256, GEMM_SMEM>>>(out);
}